// round 2
// baseline (speedup 1.0000x reference)
#include <cuda_runtime.h>

// ---------------------------------------------------------------------------
// GraphConvLayer: fused fp32 implementation
//   K0a: convert edge_index (int32 OR int64, auto-detected) -> g_src/g_dst
//   K0b: zero g_agg scratch
//   K1 : edge MLP (gather + 2-layer MLP + scatter-add)       ~33 GMAC
//   K2 : node MLP (concat + 2-layer MLP)                      ~2.5 GMAC
// ---------------------------------------------------------------------------

#define MAX_N 50000
#define MAX_E 800000
#define ND 128

// device-global scratch (allocations are forbidden)
__device__ float g_agg[(size_t)MAX_N * ND];
__device__ int   g_src[MAX_E];
__device__ int   g_dst[MAX_E];

// ---------------------------------------------------------------------------
// Index conversion. The harness may materialize the int64 edge_index as int32.
// Detect: for int64 values < 2^31, the odd int32 words (high halves) are all 0.
// For int32 data they are random node ids (all-zero probability ~ (2e-5)^16).
// ---------------------------------------------------------------------------
__global__ void convert_idx_kernel(const void* __restrict__ ei, int E)
{
    const int* p32 = (const int*)ei;
    int s = 0;
    #pragma unroll
    for (int i = 0; i < 16; ++i) s |= p32[2 * i + 1];
    const bool is64 = (s == 0);

    const int stride = gridDim.x * blockDim.x;
    if (is64) {
        const long long* p = (const long long*)ei;
        for (int i = blockIdx.x * blockDim.x + threadIdx.x; i < E; i += stride) {
            g_src[i] = (int)p[i];
            g_dst[i] = (int)p[(size_t)E + i];
        }
    } else {
        for (int i = blockIdx.x * blockDim.x + threadIdx.x; i < E; i += stride) {
            g_src[i] = p32[i];
            g_dst[i] = p32[(size_t)E + i];
        }
    }
}

__global__ void zero_agg_kernel(int n4) {
    float4 z = make_float4(0.f, 0.f, 0.f, 0.f);
    float4* p = (float4*)g_agg;
    for (int i = blockIdx.x * blockDim.x + threadIdx.x; i < n4;
         i += gridDim.x * blockDim.x)
        p[i] = z;
}

__device__ __forceinline__ float lrelu(float v) {
    return v >= 0.f ? v : 0.2f * v;
}

// ---------------------------------------------------------------------------
// Edge kernel: BE=64 edges per block, 256 threads.
// smem phase A: W1 (192x128 = 24576 f) | X (64x192 = 12288 f)   -> 147456 B
// smem phase B: H (64x128 = 8192 f) + W2 (128x128 = 16384 f) overlay W1 region
// thread (tc = tid&31, tr = tid>>5): 8 rows x 4 cols register tile
// ---------------------------------------------------------------------------
__global__ __launch_bounds__(256, 1)
void edge_mlp_kernel(const float* __restrict__ node_feats,
                     const float* __restrict__ edge_feats,
                     const float* __restrict__ w1, const float* __restrict__ b1,
                     const float* __restrict__ w2, const float* __restrict__ b2,
                     int E)
{
    extern __shared__ float sm[];
    float* sW = sm;               // phase A: W1
    float* sX = sm + 24576;       // X tile, row stride 192

    __shared__ int s_src[64];
    __shared__ int s_dst[64];

    const int tid = threadIdx.x;
    const int e0  = blockIdx.x * 64;

    if (tid < 64) {
        int e = e0 + tid;
        if (e < E) { s_src[tid] = g_src[e]; s_dst[tid] = g_dst[e]; }
        else       { s_src[tid] = -1;       s_dst[tid] = -1; }
    }
    // stage W1 (192*128 floats = 6144 float4)
    {
        const float4* g = (const float4*)w1;
        float4* s = (float4*)sW;
        for (int i = tid; i < 6144; i += 256) s[i] = g[i];
    }
    __syncthreads();

    // stage X: per edge 48 float4 (32 from node_feats[dst], 16 from edge_feats)
    for (int i = tid; i < 64 * 48; i += 256) {
        int e = i / 48, q = i - e * 48;
        float4 v = make_float4(0.f, 0.f, 0.f, 0.f);
        int d = s_dst[e];
        if (d >= 0) {
            if (q < 32) v = ((const float4*)(node_feats + (size_t)d * ND))[q];
            else        v = ((const float4*)(edge_feats + (size_t)(e0 + e) * 64))[q - 32];
        }
        ((float4*)(sX + e * 192))[q] = v;
    }
    __syncthreads();

    const int tc = tid & 31;
    const int tr = tid >> 5;
    const int r0 = tr * 8;

    // ---- GEMM1: h = lrelu(X @ W1 + b1), K = 192 ----
    float acc[8][4];
    {
        float4 bv = ((const float4*)b1)[tc];
        #pragma unroll
        for (int i = 0; i < 8; ++i) {
            acc[i][0] = bv.x; acc[i][1] = bv.y; acc[i][2] = bv.z; acc[i][3] = bv.w;
        }
    }
    {
        const float4* W4 = (const float4*)sW;   // [192][32]
        for (int k = 0; k < 192; k += 4) {
            float4 wa = W4[(k + 0) * 32 + tc];
            float4 wb = W4[(k + 1) * 32 + tc];
            float4 wc = W4[(k + 2) * 32 + tc];
            float4 wd = W4[(k + 3) * 32 + tc];
            #pragma unroll
            for (int i = 0; i < 8; ++i) {
                float4 x = ((const float4*)(sX + (r0 + i) * 192))[k >> 2];
                acc[i][0] += x.x * wa.x + x.y * wb.x + x.z * wc.x + x.w * wd.x;
                acc[i][1] += x.x * wa.y + x.y * wb.y + x.z * wc.y + x.w * wd.y;
                acc[i][2] += x.x * wa.z + x.y * wb.z + x.z * wc.z + x.w * wd.z;
                acc[i][3] += x.x * wa.w + x.y * wb.w + x.z * wc.w + x.w * wd.w;
            }
        }
    }
    #pragma unroll
    for (int i = 0; i < 8; ++i) {
        #pragma unroll
        for (int j = 0; j < 4; ++j) acc[i][j] = lrelu(acc[i][j]);
    }

    __syncthreads();   // everyone done reading sW/sX before overlay

    // ---- phase B: H + W2 overlay ----
    float* sH  = sm;          // 64x128
    float* sW2 = sm + 8192;   // 128x128
    #pragma unroll
    for (int i = 0; i < 8; ++i)
        ((float4*)(sH + (r0 + i) * ND))[tc] =
            make_float4(acc[i][0], acc[i][1], acc[i][2], acc[i][3]);
    {
        const float4* g = (const float4*)w2;
        float4* s = (float4*)sW2;
        for (int i = tid; i < 4096; i += 256) s[i] = g[i];
    }
    __syncthreads();

    // ---- GEMM2: msg = H @ W2 + b2, K = 128 ----
    float acc2[8][4];
    {
        float4 bv = ((const float4*)b2)[tc];
        #pragma unroll
        for (int i = 0; i < 8; ++i) {
            acc2[i][0] = bv.x; acc2[i][1] = bv.y; acc2[i][2] = bv.z; acc2[i][3] = bv.w;
        }
    }
    {
        const float4* W4 = (const float4*)sW2;  // [128][32]
        for (int k = 0; k < 128; k += 4) {
            float4 wa = W4[(k + 0) * 32 + tc];
            float4 wb = W4[(k + 1) * 32 + tc];
            float4 wc = W4[(k + 2) * 32 + tc];
            float4 wd = W4[(k + 3) * 32 + tc];
            #pragma unroll
            for (int i = 0; i < 8; ++i) {
                float4 x = ((const float4*)(sH + (r0 + i) * ND))[k >> 2];
                acc2[i][0] += x.x * wa.x + x.y * wb.x + x.z * wc.x + x.w * wd.x;
                acc2[i][1] += x.x * wa.y + x.y * wb.y + x.z * wc.y + x.w * wd.y;
                acc2[i][2] += x.x * wa.z + x.y * wb.z + x.z * wc.z + x.w * wd.z;
                acc2[i][3] += x.x * wa.w + x.y * wb.w + x.z * wc.w + x.w * wd.w;
            }
        }
    }

    // ---- scatter-add messages to src nodes ----
    const int c0 = tc * 4;
    #pragma unroll
    for (int i = 0; i < 8; ++i) {
        int s = s_src[r0 + i];
        if (s >= 0) {
            float* p = g_agg + (size_t)s * ND + c0;
            atomicAdd(p + 0, acc2[i][0]);
            atomicAdd(p + 1, acc2[i][1]);
            atomicAdd(p + 2, acc2[i][2]);
            atomicAdd(p + 3, acc2[i][3]);
        }
    }
}

// ---------------------------------------------------------------------------
// Node kernel: BN=64 nodes per block, 256 threads.
// smem phase A: W1 (256x128 = 32768 f) | X (64x256 = 16384 f)   -> 196608 B
// smem phase B: H (8192 f) + W2 (16384 f) overlay W1 region
// ---------------------------------------------------------------------------
__global__ __launch_bounds__(256, 1)
void node_mlp_kernel(const float* __restrict__ node_feats,
                     const float* __restrict__ w1, const float* __restrict__ b1,
                     const float* __restrict__ w2, const float* __restrict__ b2,
                     float* __restrict__ out, int N)
{
    extern __shared__ float sm[];
    float* sW = sm;               // W1 256x128
    float* sX = sm + 32768;       // X 64x256

    const int tid = threadIdx.x;
    const int n0  = blockIdx.x * 64;

    // stage W1 (8192 float4)
    {
        const float4* g = (const float4*)w1;
        float4* s = (float4*)sW;
        for (int i = tid; i < 8192; i += 256) s[i] = g[i];
    }
    // stage X: per node 64 float4 (32 node_feats + 32 g_agg)
    for (int i = tid; i < 64 * 64; i += 256) {
        int r = i >> 6, q = i & 63;
        int n = n0 + r;
        float4 v = make_float4(0.f, 0.f, 0.f, 0.f);
        if (n < N) {
            if (q < 32) v = ((const float4*)(node_feats + (size_t)n * ND))[q];
            else        v = ((const float4*)(g_agg + (size_t)n * ND))[q - 32];
        }
        ((float4*)(sX + r * 256))[q] = v;
    }
    __syncthreads();

    const int tc = tid & 31;
    const int tr = tid >> 5;
    const int r0 = tr * 8;

    // ---- GEMM1: h2 = lrelu(X @ W1 + b1), K = 256 ----
    float acc[8][4];
    {
        float4 bv = ((const float4*)b1)[tc];
        #pragma unroll
        for (int i = 0; i < 8; ++i) {
            acc[i][0] = bv.x; acc[i][1] = bv.y; acc[i][2] = bv.z; acc[i][3] = bv.w;
        }
    }
    {
        const float4* W4 = (const float4*)sW;   // [256][32]
        for (int k = 0; k < 256; k += 4) {
            float4 wa = W4[(k + 0) * 32 + tc];
            float4 wb = W4[(k + 1) * 32 + tc];
            float4 wc = W4[(k + 2) * 32 + tc];
            float4 wd = W4[(k + 3) * 32 + tc];
            #pragma unroll
            for (int i = 0; i < 8; ++i) {
                float4 x = ((const float4*)(sX + (r0 + i) * 256))[k >> 2];
                acc[i][0] += x.x * wa.x + x.y * wb.x + x.z * wc.x + x.w * wd.x;
                acc[i][1] += x.x * wa.y + x.y * wb.y + x.z * wc.y + x.w * wd.y;
                acc[i][2] += x.x * wa.z + x.y * wb.z + x.z * wc.z + x.w * wd.z;
                acc[i][3] += x.x * wa.w + x.y * wb.w + x.z * wc.w + x.w * wd.w;
            }
        }
    }
    #pragma unroll
    for (int i = 0; i < 8; ++i) {
        #pragma unroll
        for (int j = 0; j < 4; ++j) acc[i][j] = lrelu(acc[i][j]);
    }

    __syncthreads();

    float* sH  = sm;          // 64x128
    float* sW2 = sm + 8192;   // 128x128
    #pragma unroll
    for (int i = 0; i < 8; ++i)
        ((float4*)(sH + (r0 + i) * ND))[tc] =
            make_float4(acc[i][0], acc[i][1], acc[i][2], acc[i][3]);
    {
        const float4* g = (const float4*)w2;
        float4* s = (float4*)sW2;
        for (int i = tid; i < 4096; i += 256) s[i] = g[i];
    }
    __syncthreads();

    // ---- GEMM2: out = H @ W2 + b2, K = 128 ----
    float acc2[8][4];
    {
        float4 bv = ((const float4*)b2)[tc];
        #pragma unroll
        for (int i = 0; i < 8; ++i) {
            acc2[i][0] = bv.x; acc2[i][1] = bv.y; acc2[i][2] = bv.z; acc2[i][3] = bv.w;
        }
    }
    {
        const float4* W4 = (const float4*)sW2;  // [128][32]
        for (int k = 0; k < 128; k += 4) {
            float4 wa = W4[(k + 0) * 32 + tc];
            float4 wb = W4[(k + 1) * 32 + tc];
            float4 wc = W4[(k + 2) * 32 + tc];
            float4 wd = W4[(k + 3) * 32 + tc];
            #pragma unroll
            for (int i = 0; i < 8; ++i) {
                float4 x = ((const float4*)(sH + (r0 + i) * ND))[k >> 2];
                acc2[i][0] += x.x * wa.x + x.y * wb.x + x.z * wc.x + x.w * wd.x;
                acc2[i][1] += x.x * wa.y + x.y * wb.y + x.z * wc.y + x.w * wd.y;
                acc2[i][2] += x.x * wa.z + x.y * wb.z + x.z * wc.z + x.w * wd.z;
                acc2[i][3] += x.x * wa.w + x.y * wb.w + x.z * wc.w + x.w * wd.w;
            }
        }
    }

    #pragma unroll
    for (int i = 0; i < 8; ++i) {
        int n = n0 + r0 + i;
        if (n < N)
            ((float4*)(out + (size_t)n * ND))[tc] =
                make_float4(acc2[i][0], acc2[i][1], acc2[i][2], acc2[i][3]);
    }
}

// ---------------------------------------------------------------------------

extern "C" void kernel_launch(void* const* d_in, const int* in_sizes, int n_in,
                              void* d_out, int out_size)
{
    const float* node_feats = (const float*)d_in[0];
    const float* edge_feats = (const float*)d_in[1];
    const float* msg_w1     = (const float*)d_in[2];
    const float* msg_b1     = (const float*)d_in[3];
    const float* msg_w2     = (const float*)d_in[4];
    const float* msg_b2     = (const float*)d_in[5];
    const float* upd_w1     = (const float*)d_in[6];
    const float* upd_b1     = (const float*)d_in[7];
    const float* upd_w2     = (const float*)d_in[8];
    const float* upd_b2     = (const float*)d_in[9];
    const void*  edge_index = d_in[10];

    const int N = in_sizes[0] / ND;        // 50000
    const int E = in_sizes[1] / 64;        // 800000

    const int smE = (24576 + 12288) * 4;   // 147456 B
    const int smN = (32768 + 16384) * 4;   // 196608 B
    cudaFuncSetAttribute(edge_mlp_kernel, cudaFuncAttributeMaxDynamicSharedMemorySize, smE);
    cudaFuncSetAttribute(node_mlp_kernel, cudaFuncAttributeMaxDynamicSharedMemorySize, smN);

    convert_idx_kernel<<<400, 256>>>(edge_index, E);
    zero_agg_kernel<<<400, 256>>>(N * (ND / 4));

    edge_mlp_kernel<<<(E + 63) / 64, 256, smE>>>(
        node_feats, edge_feats, msg_w1, msg_b1, msg_w2, msg_b2, E);

    node_mlp_kernel<<<(N + 63) / 64, 256, smN>>>(
        node_feats, upd_w1, upd_b1, upd_w2, upd_b2,
        (float*)d_out, N);
}